// round 14
// baseline (speedup 1.0000x reference)
#include <cuda_runtime.h>
#include <math.h>

#define NN 50000
#define EE 800000
#define ET 850000          // EE + NN self loops
#define FH 128             // H * C
#define CC 64
#define NEG 0.2f
#define EPSN 1e-5f

// ---------------- scratch (static device, no allocation) ----------------
// g_xl / g_xr use a PHASE-SPLIT storage permutation:
//   storage float index s in [0,128): phase = s>>6, sub = (s>>2)&15, r = s&3
//   logical column c = (sub>>3)*64 + (sub&7)*8 + phase*4 + r
// so each attn lane's two float4 slices are contiguous 256B blocks per phase.
__device__ __align__(16) float g_xl[NN * FH];
__device__ __align__(16) float g_xr[NN * FH];
__device__ __align__(16) float g_xpre[NN * CC];
__device__ float g_cs[3 * CC];
__device__ float g_css[3 * CC];
__device__ int   g_deg[NN];
__device__ int   g_rowptr[NN + 1];
__device__ int   g_cursor[NN];
__device__ int   g_csrc[ET];

__device__ __forceinline__ float lrelu(float v) {
    return fmaxf(v, NEG * v);          // 2 ops: FMUL + FMNMX
}

// packed f32x2 helpers (Blackwell FFMA2 path, PTX-only)
typedef unsigned long long u64t;
__device__ __forceinline__ void fma2(u64t& d, u64t a, u64t b) {
    asm("fma.rn.f32x2 %0, %1, %2, %3;" : "=l"(d) : "l"(a), "l"(b), "l"(d));
}

// ================= CSR build =============================================
__global__ void k_histo(const int* __restrict__ ei) {
    int e = blockIdx.x * blockDim.x + threadIdx.x;
    if (e >= ET) return;
    int d = (e < EE) ? __ldg(ei + EE + e) : (e - EE);
    atomicAdd(&g_deg[d], 1);
}

__global__ void k_scan() {
    __shared__ int wsum[32];
    __shared__ int carry;
    int tid = threadIdx.x, lane = tid & 31, wid = tid >> 5;
    if (tid == 0) carry = 0;
    __syncthreads();
    for (int base = 0; base < NN; base += 1024) {
        int i = base + tid;
        int v = (i < NN) ? g_deg[i] : 0;
        int s = v;
#pragma unroll
        for (int off = 1; off < 32; off <<= 1) {
            int t = __shfl_up_sync(0xffffffffu, s, off);
            if (lane >= off) s += t;
        }
        if (lane == 31) wsum[wid] = s;
        __syncthreads();
        if (wid == 0) {
            int w = wsum[lane];
#pragma unroll
            for (int off = 1; off < 32; off <<= 1) {
                int t = __shfl_up_sync(0xffffffffu, w, off);
                if (lane >= off) w += t;
            }
            wsum[lane] = w;
        }
        __syncthreads();
        int boff = carry + (wid ? wsum[wid - 1] : 0);
        if (i < NN) {
            int ex = boff + s - v;
            g_rowptr[i] = ex;
            g_cursor[i] = ex;
        }
        __syncthreads();
        if (tid == 0) carry += wsum[31];
        __syncthreads();
    }
    if (tid == 0) g_rowptr[NN] = carry;
}

__global__ void k_scatter(const int* __restrict__ ei) {
    int e = blockIdx.x * blockDim.x + threadIdx.x;
    if (e >= ET) return;
    int s, d;
    if (e < EE) { s = __ldg(ei + e); d = __ldg(ei + EE + e); }
    else        { s = e - EE; d = s; }
    int pos = atomicAdd(&g_cursor[d], 1);
    g_csrc[pos] = s;
}

// zero the per-layer column stats (also shifts attn to ncu's profiled slot)
__global__ void k_zc() {
    int i = threadIdx.x;
    if (i < 3 * CC) { g_cs[i] = 0.f; g_css[i] = 0.f; }
}

// ================= per-layer kernels =====================================

// xl = x@Wl, xr = x@Wr (f32x2 FMA), prev-layer norm+relu folded into staging.
// Stores into the phase-split permuted layout: lane l writes storage floats
// 4l..4l+3, whose LOGICAL columns are c0(l)..c0(l)+3 with
// c0(l) = ((l&15)>>3)*64 + (l&7)*8 + (l>>4)*4  — so weight loads use c0(l).
__global__ void k_gemm(const float* __restrict__ xin,
                       const float* __restrict__ Wl,
                       const float* __restrict__ Wr, int din,
                       const float* __restrict__ gw,
                       const float* __restrict__ gb,
                       const float* __restrict__ gm,
                       const float* __restrict__ cs,
                       const float* __restrict__ css) {
    __shared__ float2 sx[32][CC];
    int lane = threadIdx.x;
    int tid  = threadIdx.y * 32 + lane;
    int nodeBase = blockIdx.x * 32;

    if (xin) {                         // layer 1: raw external input
        for (int idx = tid; idx < 32 * din; idx += 128) {
            int n = idx / din, k = idx % din;
            float v = (nodeBase + n < NN)
                    ? __ldg(xin + (size_t)(nodeBase + n) * din + k) : 0.f;
            sx[n][k] = make_float2(v, v);
        }
    } else {                           // din == 64: norm+relu fold
        const float invN = 1.f / (float)NN;
        for (int idx = tid; idx < 32 * CC; idx += 128) {
            int n = idx >> 6, c = idx & 63;
            float v = 0.f;
            if (nodeBase + n < NN) {
                float raw = g_xpre[(size_t)(nodeBase + n) * CC + c];
                float mu  = __ldg(cs + c)  * invN;
                float msq = __ldg(css + c) * invN;
                float ms  = __ldg(gm + c);
                float var = msq - 2.f * ms * mu * mu + ms * ms * mu * mu;
                float o = raw - ms * mu;
                v = fmaxf(__ldg(gw + c) * o * rsqrtf(var + EPSN) + __ldg(gb + c), 0.f);
            }
            sx[n][c] = make_float2(v, v);
        }
    }
    __syncthreads();

    // logical column base for this lane's 4 storage floats
    int c0 = (((lane & 15) >> 3) * 64) + ((lane & 7) * 8) + ((lane >> 4) * 4);

    int nrow = threadIdx.y * 8;
    u64t al[8][2], ar[8][2];
#pragma unroll
    for (int nn = 0; nn < 8; nn++) {
        al[nn][0] = al[nn][1] = 0ull;
        ar[nn][0] = ar[nn][1] = 0ull;
    }
    for (int k = 0; k < din; k++) {
        ulonglong2 wl = *(const ulonglong2*)(Wl + k * FH + c0);
        ulonglong2 wr = *(const ulonglong2*)(Wr + k * FH + c0);
#pragma unroll
        for (int nn = 0; nn < 8; nn++) {
            u64t xx = *(const u64t*)&sx[nrow + nn][k];
            fma2(al[nn][0], xx, wl.x);
            fma2(al[nn][1], xx, wl.y);
            fma2(ar[nn][0], xx, wr.x);
            fma2(ar[nn][1], xx, wr.y);
        }
    }
#pragma unroll
    for (int nn = 0; nn < 8; nn++) {
        int node = nodeBase + nrow + nn;
        if (node < NN) {
            ulonglong2 vl; vl.x = al[nn][0]; vl.y = al[nn][1];
            ulonglong2 vr; vr.x = ar[nn][0]; vr.y = ar[nn][1];
            *(ulonglong2*)(g_xl + (size_t)node * FH + lane * 4) = vl;
            *(ulonglong2*)(g_xr + (size_t)node * FH + lane * 4) = vr;
        }
    }
}

// Fused attention v3.2: warp per node, two parity edge-streams per warp.
// Phase-split row loads: xA = storage[0..255B] (2 lines per row),
// xB = storage[256..511B] — 8 line-wavefronts/iter instead of 16.
// Decoupled 2-level prefetch. Non-atomic column-stat finalize.
__global__ void __launch_bounds__(256, 4)
k_attn(const float* __restrict__ att,
       const float* __restrict__ b,
       float* __restrict__ cs,
       float* __restrict__ css) {
    __shared__ float sh[8][FH];
    const unsigned F = 0xffffffffu;
    int tid  = threadIdx.x;
    int warp = tid >> 5, lane = tid & 31;
    int node = blockIdx.x * 8 + warp;              // NN % 8 == 0

    int h16 = lane >> 4;                 // edge-stream (parity)
    int sub = lane & 15;
    int cbase = (sub >> 3) * CC + (sub & 7) * 8;   // LOGICAL col base
    int pA = sub * 4;                               // phase0 storage offset
    int pB = 64 + sub * 4;                          // phase1 storage offset

    float4 xr_a = *(const float4*)(g_xr + (size_t)node * FH + pA);
    float4 xr_b = *(const float4*)(g_xr + (size_t)node * FH + pB);
    float4 w_a  = *(const float4*)(att + cbase);     // logical (matches phase0)
    float4 w_b  = *(const float4*)(att + cbase + 4); // logical (matches phase1)

    int i0 = g_rowptr[node], i1 = g_rowptr[node + 1];
    int nIter = (i1 - i0 + 1) >> 1;

    float m = -INFINITY, z = 0.f;
    float4 A = make_float4(0.f, 0.f, 0.f, 0.f);
    float4 B = make_float4(0.f, 0.f, 0.f, 0.f);

    int idx = i0 + h16;
    int sc0 = __ldg(g_csrc + min(idx, i1 - 1));
    float4 xA = *(const float4*)(g_xl + (size_t)sc0 * FH + pA);
    float4 xB = *(const float4*)(g_xl + (size_t)sc0 * FH + pB);
    int sNext = __ldg(g_csrc + min(idx + 2, i1 - 1));

    for (int it = 0; it < nIter; it++) {
        bool act = idx < i1;
        float4 x0 = xA, x1 = xB;
        idx += 2;
        xA = *(const float4*)(g_xl + (size_t)sNext * FH + pA);
        xB = *(const float4*)(g_xl + (size_t)sNext * FH + pB);
        sNext = __ldg(g_csrc + min(idx + 2, i1 - 1));

        float p;
        p = lrelu(x0.x + xr_a.x) * w_a.x;
        p = fmaf(lrelu(x0.y + xr_a.y), w_a.y, p);
        p = fmaf(lrelu(x0.z + xr_a.z), w_a.z, p);
        p = fmaf(lrelu(x0.w + xr_a.w), w_a.w, p);
        p = fmaf(lrelu(x1.x + xr_b.x), w_b.x, p);
        p = fmaf(lrelu(x1.y + xr_b.y), w_b.y, p);
        p = fmaf(lrelu(x1.z + xr_b.z), w_b.z, p);
        p = fmaf(lrelu(x1.w + xr_b.w), w_b.w, p);
        p += __shfl_xor_sync(F, p, 4);   // reduce within 8-lane head group
        p += __shfl_xor_sync(F, p, 2);
        p += __shfl_xor_sync(F, p, 1);

        if (act) {
            float mn = fmaxf(m, p);
            float c  = __expf(m - mn);   // first edge: exp(-inf)=0
            float e  = __expf(p - mn);
            z = fmaf(z, c, e);
            A.x = fmaf(A.x, c, e * x0.x);  A.y = fmaf(A.y, c, e * x0.y);
            A.z = fmaf(A.z, c, e * x0.z);  A.w = fmaf(A.w, c, e * x0.w);
            B.x = fmaf(B.x, c, e * x1.x);  B.y = fmaf(B.y, c, e * x1.y);
            B.z = fmaf(B.z, c, e * x1.z);  B.w = fmaf(B.w, c, e * x1.w);
            m = mn;
        }
    }

    // merge the two parity streams (per head group)
    float mo = __shfl_xor_sync(F, m, 16);
    float zo = __shfl_xor_sync(F, z, 16);
    float4 Ao, Bo;
    Ao.x = __shfl_xor_sync(F, A.x, 16);  Ao.y = __shfl_xor_sync(F, A.y, 16);
    Ao.z = __shfl_xor_sync(F, A.z, 16);  Ao.w = __shfl_xor_sync(F, A.w, 16);
    Bo.x = __shfl_xor_sync(F, B.x, 16);  Bo.y = __shfl_xor_sync(F, B.y, 16);
    Bo.z = __shfl_xor_sync(F, B.z, 16);  Bo.w = __shfl_xor_sync(F, B.w, 16);

    float mn = fmaxf(m, mo);
    float c0 = (m  >= mn) ? 1.f : __expf(m  - mn);
    float c1 = (mo >= mn) ? 1.f : __expf(mo - mn);
    float iz = 1.f / (z * c0 + zo * c1);

    if (h16 == 0) {                      // A/B hold LOGICAL slices cbase..+7
        sh[warp][cbase + 0] = (A.x * c0 + Ao.x * c1) * iz;
        sh[warp][cbase + 1] = (A.y * c0 + Ao.y * c1) * iz;
        sh[warp][cbase + 2] = (A.z * c0 + Ao.z * c1) * iz;
        sh[warp][cbase + 3] = (A.w * c0 + Ao.w * c1) * iz;
        sh[warp][cbase + 4] = (B.x * c0 + Bo.x * c1) * iz;
        sh[warp][cbase + 5] = (B.y * c0 + Bo.y * c1) * iz;
        sh[warp][cbase + 6] = (B.z * c0 + Bo.z * c1) * iz;
        sh[warp][cbase + 7] = (B.w * c0 + Bo.w * c1) * iz;
    }
    __syncthreads();

    // 64-thread finalize: head-mean + bias, write 8 nodes, column stats
    // without any shared-memory atomics.
    if (tid < CC) {
        int c = tid;
        float bc = __ldg(b + c);
        float s = 0.f, s2 = 0.f;
        int nb = blockIdx.x * 8;
#pragma unroll
        for (int n = 0; n < 8; n++) {
            float v = 0.5f * (sh[n][c] + sh[n][CC + c]) + bc;
            g_xpre[(size_t)(nb + n) * CC + c] = v;
            s += v;
            s2 = fmaf(v, v, s2);
        }
        atomicAdd(&cs[c],  s);
        atomicAdd(&css[c], s2);
    }
}

// final graph norm + relu (layer 3 only)
__global__ void k_norm(const float* __restrict__ gw,
                       const float* __restrict__ gb,
                       const float* __restrict__ gm,
                       const float* __restrict__ cs,
                       const float* __restrict__ css,
                       float* __restrict__ out) {
    int idx = blockIdx.x * blockDim.x + threadIdx.x;
    int c = idx & 63;
    float inv = 1.f / (float)NN;
    float mu  = __ldg(cs + c)  * inv;
    float msq = __ldg(css + c) * inv;
    float ms  = __ldg(gm + c);
    float var = msq - 2.f * ms * mu * mu + ms * ms * mu * mu;
    float o = g_xpre[idx] - ms * mu;
    float y = __ldg(gw + c) * o * rsqrtf(var + EPSN) + __ldg(gb + c);
    out[idx] = fmaxf(y, 0.f);
}

// ---------------- launch ----------------
extern "C" void kernel_launch(void* const* d_in, const int* in_sizes, int n_in,
                              void* d_out, int out_size) {
    const float* x  = (const float*)d_in[0];
    const int*   ei = (const int*)d_in[1];
    float* out = (float*)d_out;

    float *cs0, *css0; int* dDeg;
    cudaGetSymbolAddress((void**)&cs0,  g_cs);
    cudaGetSymbolAddress((void**)&css0, g_css);
    cudaGetSymbolAddress((void**)&dDeg, g_deg);

    static cudaStream_t s2 = nullptr;
    static cudaEvent_t evA = nullptr, evB = nullptr;
    if (!s2) {
        cudaStreamCreateWithFlags(&s2, cudaStreamNonBlocking);
        cudaEventCreateWithFlags(&evA, cudaEventDisableTiming);
        cudaEventCreateWithFlags(&evB, cudaEventDisableTiming);
    }

    const int edgeBlocks = (ET + 255) / 256;       // 3321
    const int gemmBlocks = (NN + 31) / 32;         // 1563
    const int attnBlocks = NN / 8;                 // 6250
    const int normBlocks = (NN * CC) / 256;        // 12500

    // fork: CSR build on s2, overlapped with layer-1 GEMM
    cudaEventRecord(evA, 0);
    cudaStreamWaitEvent(s2, evA, 0);
    cudaMemsetAsync(dDeg, 0, NN * sizeof(int), s2);
    k_histo<<<edgeBlocks, 256, 0, s2>>>(ei);
    k_scan<<<1, 1024, 0, s2>>>();
    k_scatter<<<edgeBlocks, 256, 0, s2>>>(ei);
    cudaEventRecord(evB, s2);

    k_zc<<<1, 256>>>();

    const float* xin = x;
    int din = 3;
    const float *pgw = nullptr, *pgb = nullptr, *pgm = nullptr;
    for (int l = 0; l < 3; l++) {
        int base = 2 + 7 * l;
        const float* Wl  = (const float*)d_in[base + 0];
        const float* Wr  = (const float*)d_in[base + 1];
        const float* att = (const float*)d_in[base + 2];
        const float* b   = (const float*)d_in[base + 3];

        float* csP  = cs0  + (l > 0 ? (l - 1) * CC : 0);
        float* cssP = css0 + (l > 0 ? (l - 1) * CC : 0);
        k_gemm<<<gemmBlocks, dim3(32, 4)>>>(xin, Wl, Wr, din,
                                            pgw, pgb, pgm, csP, cssP);
        if (l == 0) cudaStreamWaitEvent(0, evB, 0);
        k_attn<<<attnBlocks, 256>>>(att, b, cs0 + l * CC, css0 + l * CC);

        pgw = (const float*)d_in[base + 4];
        pgb = (const float*)d_in[base + 5];
        pgm = (const float*)d_in[base + 6];
        xin = nullptr;
        din = CC;
    }
    k_norm<<<normBlocks, 256>>>(pgw, pgb, pgm,
                                cs0 + 2 * CC, css0 + 2 * CC, out);
}

// round 16
// speedup vs baseline: 1.4539x; 1.4539x over previous
#include <cuda_runtime.h>
#include <math.h>

#define NN 50000
#define EE 800000
#define ET 850000          // EE + NN self loops
#define FH 128             // H * C
#define CC 64
#define NEG 0.2f
#define EPSN 1e-5f

// ---------------- scratch (static device, no allocation) ----------------
__device__ __align__(16) float g_xl[NN * FH];
__device__ __align__(16) float g_xr[NN * FH];
__device__ __align__(16) float g_xpre[NN * CC];
__device__ float g_cs[3 * CC];
__device__ float g_css[3 * CC];
__device__ int   g_deg[NN];
__device__ int   g_rowptr[NN + 1];
__device__ int   g_cursor[NN];
__device__ int   g_csrc[ET];

__device__ __forceinline__ float lrelu(float v) {
    return fmaxf(v, NEG * v);          // 2 ops: FMUL + FMNMX
}

// packed f32x2 helpers (Blackwell FFMA2 path, PTX-only)
typedef unsigned long long u64t;
__device__ __forceinline__ void fma2(u64t& d, u64t a, u64t b) {
    asm("fma.rn.f32x2 %0, %1, %2, %3;" : "=l"(d) : "l"(a), "l"(b), "l"(d));
}

// ================= CSR build =============================================
__global__ void k_histo(const int* __restrict__ ei) {
    int e = blockIdx.x * blockDim.x + threadIdx.x;
    if (e >= ET) return;
    int d = (e < EE) ? __ldg(ei + EE + e) : (e - EE);
    atomicAdd(&g_deg[d], 1);
}

__global__ void k_scan() {
    __shared__ int wsum[32];
    __shared__ int carry;
    int tid = threadIdx.x, lane = tid & 31, wid = tid >> 5;
    if (tid == 0) carry = 0;
    __syncthreads();
    for (int base = 0; base < NN; base += 1024) {
        int i = base + tid;
        int v = (i < NN) ? g_deg[i] : 0;
        int s = v;
#pragma unroll
        for (int off = 1; off < 32; off <<= 1) {
            int t = __shfl_up_sync(0xffffffffu, s, off);
            if (lane >= off) s += t;
        }
        if (lane == 31) wsum[wid] = s;
        __syncthreads();
        if (wid == 0) {
            int w = wsum[lane];
#pragma unroll
            for (int off = 1; off < 32; off <<= 1) {
                int t = __shfl_up_sync(0xffffffffu, w, off);
                if (lane >= off) w += t;
            }
            wsum[lane] = w;
        }
        __syncthreads();
        int boff = carry + (wid ? wsum[wid - 1] : 0);
        if (i < NN) {
            int ex = boff + s - v;
            g_rowptr[i] = ex;
            g_cursor[i] = ex;
        }
        __syncthreads();
        if (tid == 0) carry += wsum[31];
        __syncthreads();
    }
    if (tid == 0) g_rowptr[NN] = carry;
}

__global__ void k_scatter(const int* __restrict__ ei) {
    int e = blockIdx.x * blockDim.x + threadIdx.x;
    if (e >= ET) return;
    int s, d;
    if (e < EE) { s = __ldg(ei + e); d = __ldg(ei + EE + e); }
    else        { s = e - EE; d = s; }
    int pos = atomicAdd(&g_cursor[d], 1);
    g_csrc[pos] = s;
}

// ================= per-layer kernels =====================================

// xl = x@Wl, xr = x@Wr (f32x2 FMA), prev-layer norm+relu folded into staging.
// UNCHANGED from the proven R13 version (at the FFMA2 roofline, regs=127).
__global__ void k_gemm(const float* __restrict__ xin,
                       const float* __restrict__ Wl,
                       const float* __restrict__ Wr, int din,
                       const float* __restrict__ gw,
                       const float* __restrict__ gb,
                       const float* __restrict__ gm,
                       const float* __restrict__ cs,
                       const float* __restrict__ css) {
    __shared__ float2 sx[32][CC];
    int lane = threadIdx.x;
    int tid  = threadIdx.y * 32 + lane;
    int nodeBase = blockIdx.x * 32;

    if (xin) {                         // layer 1: raw external input
        for (int idx = tid; idx < 32 * din; idx += 128) {
            int n = idx / din, k = idx % din;
            float v = (nodeBase + n < NN)
                    ? __ldg(xin + (size_t)(nodeBase + n) * din + k) : 0.f;
            sx[n][k] = make_float2(v, v);
        }
    } else {                           // din == 64: norm+relu fold
        const float invN = 1.f / (float)NN;
        for (int idx = tid; idx < 32 * CC; idx += 128) {
            int n = idx >> 6, c = idx & 63;
            float v = 0.f;
            if (nodeBase + n < NN) {
                float raw = g_xpre[(size_t)(nodeBase + n) * CC + c];
                float mu  = __ldg(cs + c)  * invN;
                float msq = __ldg(css + c) * invN;
                float ms  = __ldg(gm + c);
                float var = msq - 2.f * ms * mu * mu + ms * ms * mu * mu;
                float o = raw - ms * mu;
                v = fmaxf(__ldg(gw + c) * o * rsqrtf(var + EPSN) + __ldg(gb + c), 0.f);
            }
            sx[n][c] = make_float2(v, v);
        }
    }
    __syncthreads();

    int nrow = threadIdx.y * 8;
    u64t al[8][2], ar[8][2];
#pragma unroll
    for (int nn = 0; nn < 8; nn++) {
        al[nn][0] = al[nn][1] = 0ull;
        ar[nn][0] = ar[nn][1] = 0ull;
    }
    for (int k = 0; k < din; k++) {
        ulonglong2 wl = *(const ulonglong2*)(Wl + k * FH + lane * 4);
        ulonglong2 wr = *(const ulonglong2*)(Wr + k * FH + lane * 4);
#pragma unroll
        for (int nn = 0; nn < 8; nn++) {
            u64t xx = *(const u64t*)&sx[nrow + nn][k];
            fma2(al[nn][0], xx, wl.x);
            fma2(al[nn][1], xx, wl.y);
            fma2(ar[nn][0], xx, wr.x);
            fma2(ar[nn][1], xx, wr.y);
        }
    }
#pragma unroll
    for (int nn = 0; nn < 8; nn++) {
        int node = nodeBase + nrow + nn;
        if (node < NN) {
            ulonglong2 vl; vl.x = al[nn][0]; vl.y = al[nn][1];
            ulonglong2 vr; vr.x = ar[nn][0]; vr.y = ar[nn][1];
            *(ulonglong2*)(g_xl + (size_t)node * FH + lane * 4) = vl;
            *(ulonglong2*)(g_xr + (size_t)node * FH + lane * 4) = vr;
        }
    }
}

// Fused attention v3.3: warp per node, two parity edge-streams per warp
// (lanes 0-15 even CSR slots, 16-31 odd). TWO-DEEP row pipeline: rows for
// iters t and t+1 resident, row load for t+2 issued each iter; index
// stream runs three pairs ahead. Non-atomic column-stat finalize.
__global__ void __launch_bounds__(256, 3)
k_attn(const float* __restrict__ att,
       const float* __restrict__ b,
       float* __restrict__ cs,
       float* __restrict__ css) {
    __shared__ float sh[8][FH];
    const unsigned F = 0xffffffffu;
    int tid  = threadIdx.x;
    int warp = tid >> 5, lane = tid & 31;
    int node = blockIdx.x * 8 + warp;              // NN % 8 == 0

    int h16 = lane >> 4;                 // edge-stream (parity)
    int sub = lane & 15;
    int cbase = (sub >> 3) * CC + (sub & 7) * 8;   // head*64 + q*8

    float4 xr_a = *(const float4*)(g_xr + (size_t)node * FH + cbase);
    float4 xr_b = *(const float4*)(g_xr + (size_t)node * FH + cbase + 4);
    float4 w_a  = *(const float4*)(att + cbase);
    float4 w_b  = *(const float4*)(att + cbase + 4);

    int i0 = g_rowptr[node], i1 = g_rowptr[node + 1];
    int nIter = (i1 - i0 + 1) >> 1;

    float m = -INFINITY, z = 0.f;
    float4 A = make_float4(0.f, 0.f, 0.f, 0.f);
    float4 B = make_float4(0.f, 0.f, 0.f, 0.f);

    int idx = i0 + h16;
    // prologue: rows for iter 0 and 1 in flight, index for iter 2 resident
    int s0 = __ldg(g_csrc + min(idx,     i1 - 1));
    int s1 = __ldg(g_csrc + min(idx + 2, i1 - 1));
    float4 r0a = *(const float4*)(g_xl + (size_t)s0 * FH + cbase);
    float4 r0b = *(const float4*)(g_xl + (size_t)s0 * FH + cbase + 4);
    float4 r1a = *(const float4*)(g_xl + (size_t)s1 * FH + cbase);
    float4 r1b = *(const float4*)(g_xl + (size_t)s1 * FH + cbase + 4);
    int s2 = __ldg(g_csrc + min(idx + 4, i1 - 1));

    for (int it = 0; it < nIter; it++) {
        bool act = idx < i1;
        float4 x0 = r0a, x1 = r0b;
        idx += 2;
        // rotate pipeline: r0 <- r1, issue row load for iter t+2
        r0a = r1a;  r0b = r1b;
        r1a = *(const float4*)(g_xl + (size_t)s2 * FH + cbase);
        r1b = *(const float4*)(g_xl + (size_t)s2 * FH + cbase + 4);
        s2 = __ldg(g_csrc + min(idx + 4, i1 - 1));

        float p;
        p = lrelu(x0.x + xr_a.x) * w_a.x;
        p = fmaf(lrelu(x0.y + xr_a.y), w_a.y, p);
        p = fmaf(lrelu(x0.z + xr_a.z), w_a.z, p);
        p = fmaf(lrelu(x0.w + xr_a.w), w_a.w, p);
        p = fmaf(lrelu(x1.x + xr_b.x), w_b.x, p);
        p = fmaf(lrelu(x1.y + xr_b.y), w_b.y, p);
        p = fmaf(lrelu(x1.z + xr_b.z), w_b.z, p);
        p = fmaf(lrelu(x1.w + xr_b.w), w_b.w, p);
        p += __shfl_xor_sync(F, p, 4);   // reduce within 8-lane head group
        p += __shfl_xor_sync(F, p, 2);
        p += __shfl_xor_sync(F, p, 1);

        if (act) {
            float mn = fmaxf(m, p);
            float c  = __expf(m - mn);   // first edge: exp(-inf)=0
            float e  = __expf(p - mn);
            z = fmaf(z, c, e);
            A.x = fmaf(A.x, c, e * x0.x);  A.y = fmaf(A.y, c, e * x0.y);
            A.z = fmaf(A.z, c, e * x0.z);  A.w = fmaf(A.w, c, e * x0.w);
            B.x = fmaf(B.x, c, e * x1.x);  B.y = fmaf(B.y, c, e * x1.y);
            B.z = fmaf(B.z, c, e * x1.z);  B.w = fmaf(B.w, c, e * x1.w);
            m = mn;
        }
    }

    // merge the two parity streams' softmax states (per head group)
    float mo = __shfl_xor_sync(F, m, 16);
    float zo = __shfl_xor_sync(F, z, 16);
    float4 Ao, Bo;
    Ao.x = __shfl_xor_sync(F, A.x, 16);  Ao.y = __shfl_xor_sync(F, A.y, 16);
    Ao.z = __shfl_xor_sync(F, A.z, 16);  Ao.w = __shfl_xor_sync(F, A.w, 16);
    Bo.x = __shfl_xor_sync(F, B.x, 16);  Bo.y = __shfl_xor_sync(F, B.y, 16);
    Bo.z = __shfl_xor_sync(F, B.z, 16);  Bo.w = __shfl_xor_sync(F, B.w, 16);

    float mn = fmaxf(m, mo);
    float c0 = (m  >= mn) ? 1.f : __expf(m  - mn);
    float c1 = (mo >= mn) ? 1.f : __expf(mo - mn);
    float iz = 1.f / (z * c0 + zo * c1);

    if (h16 == 0) {
        sh[warp][cbase + 0] = (A.x * c0 + Ao.x * c1) * iz;
        sh[warp][cbase + 1] = (A.y * c0 + Ao.y * c1) * iz;
        sh[warp][cbase + 2] = (A.z * c0 + Ao.z * c1) * iz;
        sh[warp][cbase + 3] = (A.w * c0 + Ao.w * c1) * iz;
        sh[warp][cbase + 4] = (B.x * c0 + Bo.x * c1) * iz;
        sh[warp][cbase + 5] = (B.y * c0 + Bo.y * c1) * iz;
        sh[warp][cbase + 6] = (B.z * c0 + Bo.z * c1) * iz;
        sh[warp][cbase + 7] = (B.w * c0 + Bo.w * c1) * iz;
    }
    __syncthreads();

    // 64-thread finalize: head-mean + bias, write 8 nodes, column stats
    // without shared-memory atomics (8 serial adds per column).
    if (tid < CC) {
        int c = tid;
        float bc = __ldg(b + c);
        float s = 0.f, s2 = 0.f;
        int nb = blockIdx.x * 8;
#pragma unroll
        for (int n = 0; n < 8; n++) {
            float v = 0.5f * (sh[n][c] + sh[n][CC + c]) + bc;
            g_xpre[(size_t)(nb + n) * CC + c] = v;
            s += v;
            s2 = fmaf(v, v, s2);
        }
        atomicAdd(&cs[c],  s);
        atomicAdd(&css[c], s2);
    }
}

// final graph norm + relu (layer 3 only)
__global__ void k_norm(const float* __restrict__ gw,
                       const float* __restrict__ gb,
                       const float* __restrict__ gm,
                       const float* __restrict__ cs,
                       const float* __restrict__ css,
                       float* __restrict__ out) {
    int idx = blockIdx.x * blockDim.x + threadIdx.x;
    int c = idx & 63;
    float inv = 1.f / (float)NN;
    float mu  = __ldg(cs + c)  * inv;
    float msq = __ldg(css + c) * inv;
    float ms  = __ldg(gm + c);
    float var = msq - 2.f * ms * mu * mu + ms * ms * mu * mu;
    float o = g_xpre[idx] - ms * mu;
    float y = __ldg(gw + c) * o * rsqrtf(var + EPSN) + __ldg(gb + c);
    out[idx] = fmaxf(y, 0.f);
}

// ---------------- launch ----------------
extern "C" void kernel_launch(void* const* d_in, const int* in_sizes, int n_in,
                              void* d_out, int out_size) {
    const float* x  = (const float*)d_in[0];
    const int*   ei = (const int*)d_in[1];
    float* out = (float*)d_out;

    float *cs0, *css0; int* dDeg;
    cudaGetSymbolAddress((void**)&cs0,  g_cs);
    cudaGetSymbolAddress((void**)&css0, g_css);
    cudaGetSymbolAddress((void**)&dDeg, g_deg);

    static cudaStream_t s2 = nullptr;
    static cudaEvent_t evA = nullptr, evB = nullptr;
    if (!s2) {
        cudaStreamCreateWithFlags(&s2, cudaStreamNonBlocking);
        cudaEventCreateWithFlags(&evA, cudaEventDisableTiming);
        cudaEventCreateWithFlags(&evB, cudaEventDisableTiming);
    }

    const int edgeBlocks = (ET + 255) / 256;       // 3321
    const int gemmBlocks = (NN + 31) / 32;         // 1563
    const int attnBlocks = NN / 8;                 // 6250
    const int normBlocks = (NN * CC) / 256;        // 12500

    // fork: CSR build on s2, overlapped with layer-1 GEMM
    cudaEventRecord(evA, 0);
    cudaStreamWaitEvent(s2, evA, 0);
    cudaMemsetAsync(dDeg, 0, NN * sizeof(int), s2);
    k_histo<<<edgeBlocks, 256, 0, s2>>>(ei);
    k_scan<<<1, 1024, 0, s2>>>();
    k_scatter<<<edgeBlocks, 256, 0, s2>>>(ei);
    cudaEventRecord(evB, s2);

    cudaMemsetAsync(cs0,  0, 3 * CC * sizeof(float), 0);
    cudaMemsetAsync(css0, 0, 3 * CC * sizeof(float), 0);

    const float* xin = x;
    int din = 3;
    const float *pgw = nullptr, *pgb = nullptr, *pgm = nullptr;
    for (int l = 0; l < 3; l++) {
        int base = 2 + 7 * l;
        const float* Wl  = (const float*)d_in[base + 0];
        const float* Wr  = (const float*)d_in[base + 1];
        const float* att = (const float*)d_in[base + 2];
        const float* b   = (const float*)d_in[base + 3];

        float* csP  = cs0  + (l > 0 ? (l - 1) * CC : 0);
        float* cssP = css0 + (l > 0 ? (l - 1) * CC : 0);
        k_gemm<<<gemmBlocks, dim3(32, 4)>>>(xin, Wl, Wr, din,
                                            pgw, pgb, pgm, csP, cssP);
        if (l == 0) cudaStreamWaitEvent(0, evB, 0);
        k_attn<<<attnBlocks, 256>>>(att, b, cs0 + l * CC, css0 + l * CC);

        pgw = (const float*)d_in[base + 4];
        pgb = (const float*)d_in[base + 5];
        pgm = (const float*)d_in[base + 6];
        xin = nullptr;
        din = CC;
    }
    k_norm<<<normBlocks, 256>>>(pgw, pgb, pgm,
                                cs0 + 2 * CC, css0 + 2 * CC, out);
}